// round 1
// baseline (speedup 1.0000x reference)
#include <cuda_runtime.h>

#define NN 4096
#define DD 128
#define HH 8
#define ALPHA 0.2f
#define EPSLN 1e-5f

// ---- scratch (static device globals: no allocation in kernel_launch) ----
__device__ float g_Wh[HH * NN * DD];    // [h][n][e]  16MB
__device__ float g_attn[HH * NN * DD];  // normalized attention out (pre-ELU)
__device__ float g_f1[HH * NN];
__device__ float g_f2[HH * NN];
__device__ float g_f2t[NN * HH];        // [n][h] for vectorized rowmax gather
__device__ float g_rowmax[HH * NN];

// ============================================================
// K1: Wh[h,n,e] = sum_d nodes[n,d] * W[h,d,e]
// grid (N/32, H), 128 threads; thread = output column e, 32 rows in regs.
// ============================================================
__global__ void __launch_bounds__(128) k_wh(const float* __restrict__ nodes,
                                            const float* __restrict__ W) {
    int h = blockIdx.y;
    int n0 = blockIdx.x * 32;
    int e = threadIdx.x;
    __shared__ float xs[32][DD];
#pragma unroll
    for (int r = 0; r < 32; ++r) xs[r][e] = nodes[(n0 + r) * DD + e];
    __syncthreads();
    float acc[32];
#pragma unroll
    for (int r = 0; r < 32; ++r) acc[r] = 0.f;
    const float* Wp = W + h * DD * DD + e;
    for (int k = 0; k < DD; k += 4) {
        float w0 = Wp[(k + 0) * DD];
        float w1 = Wp[(k + 1) * DD];
        float w2 = Wp[(k + 2) * DD];
        float w3 = Wp[(k + 3) * DD];
#pragma unroll
        for (int r = 0; r < 32; ++r) {
            float4 x4 = *(const float4*)&xs[r][k];
            float a = acc[r];
            a = fmaf(x4.x, w0, a);
            a = fmaf(x4.y, w1, a);
            a = fmaf(x4.z, w2, a);
            a = fmaf(x4.w, w3, a);
            acc[r] = a;
        }
    }
#pragma unroll
    for (int r = 0; r < 32; ++r) g_Wh[(h * NN + n0 + r) * DD + e] = acc[r];
}

// ============================================================
// K1b: f1[h,n] = Wh[h,n,:].a1[h]; f2 likewise; also f2 transposed [n][h].
// One warp per (h,n). grid 4096 x 256 threads.
// ============================================================
__global__ void __launch_bounds__(256) k_f(const float* __restrict__ a1,
                                           const float* __restrict__ a2) {
    int warp = (blockIdx.x * blockDim.x + threadIdx.x) >> 5;
    int lane = threadIdx.x & 31;
    int h = warp >> 12;   // /4096
    int n = warp & (NN - 1);
    float4 wv = *(const float4*)&g_Wh[(h * NN + n) * DD + lane * 4];
    float4 av = *(const float4*)&a1[h * DD + lane * 4];
    float4 bv = *(const float4*)&a2[h * DD + lane * 4];
    float s1 = wv.x * av.x + wv.y * av.y + wv.z * av.z + wv.w * av.w;
    float s2 = wv.x * bv.x + wv.y * bv.y + wv.z * bv.z + wv.w * bv.w;
#pragma unroll
    for (int o = 16; o; o >>= 1) {
        s1 += __shfl_xor_sync(0xffffffffu, s1, o);
        s2 += __shfl_xor_sync(0xffffffffu, s2, o);
    }
    if (lane == 0) {
        g_f1[h * NN + n] = s1;
        g_f2[h * NN + n] = s2;
        g_f2t[n * HH + h] = s2;
    }
}

// ============================================================
// K2: rowmax[h,n] = max over {m : adj[n,m]>0} of f2[h,m]  (all 8 heads in one adj pass)
// grid N, 256 threads.
// ============================================================
__global__ void __launch_bounds__(256) k_rowmax(const int* __restrict__ adj) {
    int n = blockIdx.x;
    int t = threadIdx.x;
    float mx[8];
#pragma unroll
    for (int i = 0; i < 8; ++i) mx[i] = -1e30f;
    const int* arow = adj + (long long)n * NN;
    for (int m = t; m < NN; m += 256) {
        if (arow[m] > 0) {
            float4 fa = *(const float4*)&g_f2t[m * HH];
            float4 fb = *(const float4*)&g_f2t[m * HH + 4];
            mx[0] = fmaxf(mx[0], fa.x);
            mx[1] = fmaxf(mx[1], fa.y);
            mx[2] = fmaxf(mx[2], fa.z);
            mx[3] = fmaxf(mx[3], fa.w);
            mx[4] = fmaxf(mx[4], fb.x);
            mx[5] = fmaxf(mx[5], fb.y);
            mx[6] = fmaxf(mx[6], fb.z);
            mx[7] = fmaxf(mx[7], fb.w);
        }
    }
#pragma unroll
    for (int i = 0; i < 8; ++i)
#pragma unroll
        for (int o = 16; o; o >>= 1) mx[i] = fmaxf(mx[i], __shfl_xor_sync(0xffffffffu, mx[i], o));
    __shared__ float smx[8][8];
    if ((t & 31) == 0) {
        int w = t >> 5;
#pragma unroll
        for (int i = 0; i < 8; ++i) smx[w][i] = mx[i];
    }
    __syncthreads();
    if (t < 8) {
        float m = smx[0][t];
#pragma unroll
        for (int w = 1; w < 8; ++w) m = fmaxf(m, smx[w][t]);
        g_rowmax[t * NN + n] = m;
    }
}

// ============================================================
// K3: fused masked-softmax aggregation (dominant kernel).
// out[h,n,:] = sum_m p(h,n,m) Wh[h,m,:] / sum_m p, p = exp(lrelu(f1+f2m)-mx) or 0.
// Block: (h = blockIdx.x fast so heads share adj in L2, n-tile = blockIdx.y).
// Per chunk of 128 m: phase1 fills P[32][129] in smem, phase2 register-tiled accumulate.
// ============================================================
__global__ void __launch_bounds__(256) k_attn(const int* __restrict__ adj) {
    int h = blockIdx.x;
    int n0 = blockIdx.y * 32;
    int t = threadIdx.x;
    __shared__ float Ps[32][129];   // padded: rows ty / ty+16 land in different banks
    __shared__ float sc_f1[32], sc_mx[32];
    if (t < 32) {
        float f1v = g_f1[h * NN + n0 + t];
        float rm = g_rowmax[h * NN + n0 + t];
        float s = f1v + rm;
        sc_f1[t] = f1v;
        sc_mx[t] = s > 0.f ? s : ALPHA * s;  // lrelu monotone -> max of scores
    }
    int tx = t & 15, ty = t >> 4;       // 16 lanes over e, 16 ty over rows
    int e0 = tx * 4;
    float4 aA0 = {0, 0, 0, 0}, aB0 = {0, 0, 0, 0};
    float4 aA1 = {0, 0, 0, 0}, aB1 = {0, 0, 0, 0};
    float sacc0 = 0.f, sacc1 = 0.f;
    int mm = t & 127, half = t >> 7;
    const float* f2p = g_f2 + h * NN;

    for (int m0 = 0; m0 < NN; m0 += 128) {
        __syncthreads();  // prev phase-2 reads done (and initial smem writes visible)
        // phase 1: P tile
        float f2v = f2p[m0 + mm];
#pragma unroll
        for (int i = 0; i < 16; ++i) {
            int r = half * 16 + i;
            int a = adj[(n0 + r) * NN + m0 + mm];
            float s = sc_f1[r] + f2v;
            s = s > 0.f ? s : ALPHA * s;
            float p = (a > 0) ? __expf(s - sc_mx[r]) : 0.f;
            Ps[r][mm] = p;
        }
        __syncthreads();
        // phase 2: acc += P * Wh  (each thread: rows {ty, ty+16}, cols {e0..e0+3, e0+64..e0+67})
        const float* whb = g_Wh + (h * NN + m0) * DD;
#pragma unroll 4
        for (int k = 0; k < 128; ++k) {
            float4 w0 = *(const float4*)&whb[k * DD + e0];
            float4 w1 = *(const float4*)&whb[k * DD + e0 + 64];
            float p0 = Ps[ty][k];
            float p1 = Ps[ty + 16][k];
            sacc0 += p0;
            sacc1 += p1;
            aA0.x = fmaf(p0, w0.x, aA0.x); aA0.y = fmaf(p0, w0.y, aA0.y);
            aA0.z = fmaf(p0, w0.z, aA0.z); aA0.w = fmaf(p0, w0.w, aA0.w);
            aB0.x = fmaf(p0, w1.x, aB0.x); aB0.y = fmaf(p0, w1.y, aB0.y);
            aB0.z = fmaf(p0, w1.z, aB0.z); aB0.w = fmaf(p0, w1.w, aB0.w);
            aA1.x = fmaf(p1, w0.x, aA1.x); aA1.y = fmaf(p1, w0.y, aA1.y);
            aA1.z = fmaf(p1, w0.z, aA1.z); aA1.w = fmaf(p1, w0.w, aA1.w);
            aB1.x = fmaf(p1, w1.x, aB1.x); aB1.y = fmaf(p1, w1.y, aB1.y);
            aB1.z = fmaf(p1, w1.z, aB1.z); aB1.w = fmaf(p1, w1.w, aB1.w);
        }
    }
    float inv0 = 1.f / sacc0;
    float inv1 = 1.f / sacc1;
    float* o0 = g_attn + (h * NN + n0 + ty) * DD;
    float* o1 = g_attn + (h * NN + n0 + ty + 16) * DD;
    float4 r;
    r.x = aA0.x * inv0; r.y = aA0.y * inv0; r.z = aA0.z * inv0; r.w = aA0.w * inv0;
    *(float4*)&o0[e0] = r;
    r.x = aB0.x * inv0; r.y = aB0.y * inv0; r.z = aB0.z * inv0; r.w = aB0.w * inv0;
    *(float4*)&o0[e0 + 64] = r;
    r.x = aA1.x * inv1; r.y = aA1.y * inv1; r.z = aA1.z * inv1; r.w = aA1.w * inv1;
    *(float4*)&o1[e0] = r;
    r.x = aB1.x * inv1; r.y = aB1.y * inv1; r.z = aB1.z * inv1; r.w = aB1.w * inv1;
    *(float4*)&o1[e0 + 64] = r;
}

// ============================================================
// K4: x = elu(elu(cat) @ W1 + b1); out = LayerNorm(nodes + x) * gamma + beta
// cat[n, h*128+e] = elu(g_attn[h][n][e]) applied at A-load.
// Block: 32 rows, full 128 output cols. Warp owns 4 rows (full row in warp -> shfl LN).
// ============================================================
__global__ void __launch_bounds__(256) k_final(const float* __restrict__ nodes,
                                               const float* __restrict__ W1,
                                               const float* __restrict__ b1,
                                               const float* __restrict__ gamma,
                                               const float* __restrict__ beta,
                                               float* __restrict__ out) {
    int n0 = blockIdx.x * 32;
    int t = threadIdx.x;
    int lane = t & 31, w = t >> 5;
    int e2 = lane * 4;
    __shared__ float As[32][64];
    __shared__ float Bs[64][DD];
    float4 acc[4];
#pragma unroll
    for (int rr = 0; rr < 4; ++rr) acc[rr] = make_float4(0.f, 0.f, 0.f, 0.f);

    for (int k0 = 0; k0 < HH * DD; k0 += 64) {
        __syncthreads();
        for (int idx = t; idx < 32 * 64; idx += 256) {
            int row = idx >> 6, kk = idx & 63;
            int k = k0 + kk;
            int hh = k >> 7, e = k & 127;
            float v = g_attn[(hh * NN + n0 + row) * DD + e];
            As[row][kk] = v > 0.f ? v : expm1f(v);  // first ELU
        }
        for (int idx = t; idx < 64 * DD; idx += 256) {
            int kk = idx >> 7, e = idx & 127;
            Bs[kk][e] = W1[(k0 + kk) * DD + e];
        }
        __syncthreads();
#pragma unroll 4
        for (int kk = 0; kk < 64; ++kk) {
            float4 b4 = *(const float4*)&Bs[kk][e2];
#pragma unroll
            for (int rr = 0; rr < 4; ++rr) {
                float a = As[w * 4 + rr][kk];
                acc[rr].x = fmaf(a, b4.x, acc[rr].x);
                acc[rr].y = fmaf(a, b4.y, acc[rr].y);
                acc[rr].z = fmaf(a, b4.z, acc[rr].z);
                acc[rr].w = fmaf(a, b4.w, acc[rr].w);
            }
        }
    }

    float4 bb = *(const float4*)&b1[e2];
    float4 gg = *(const float4*)&gamma[e2];
    float4 be = *(const float4*)&beta[e2];
#pragma unroll
    for (int rr = 0; rr < 4; ++rr) {
        int n = n0 + w * 4 + rr;
        float4 x = acc[rr];
        x.x += bb.x; x.y += bb.y; x.z += bb.z; x.w += bb.w;
        x.x = x.x > 0.f ? x.x : expm1f(x.x);    // second ELU
        x.y = x.y > 0.f ? x.y : expm1f(x.y);
        x.z = x.z > 0.f ? x.z : expm1f(x.z);
        x.w = x.w > 0.f ? x.w : expm1f(x.w);
        float4 nd = *(const float4*)&nodes[n * DD + e2];
        float4 y = make_float4(nd.x + x.x, nd.y + x.y, nd.z + x.z, nd.w + x.w);
        float s = y.x + y.y + y.z + y.w;
        float q = y.x * y.x + y.y * y.y + y.z * y.z + y.w * y.w;
#pragma unroll
        for (int o = 16; o; o >>= 1) {
            s += __shfl_xor_sync(0xffffffffu, s, o);
            q += __shfl_xor_sync(0xffffffffu, q, o);
        }
        float mu = s * (1.f / 128.f);
        float var = q * (1.f / 128.f) - mu * mu;
        float rs = rsqrtf(var + EPSLN);
        float4 o4;
        o4.x = (y.x - mu) * rs * gg.x + be.x;
        o4.y = (y.y - mu) * rs * gg.y + be.y;
        o4.z = (y.z - mu) * rs * gg.z + be.z;
        o4.w = (y.w - mu) * rs * gg.w + be.w;
        *(float4*)&out[n * DD + e2] = o4;
    }
}

extern "C" void kernel_launch(void* const* d_in, const int* in_sizes, int n_in,
                              void* d_out, int out_size) {
    const float* nodes = (const float*)d_in[0];
    const int* adj = (const int*)d_in[1];
    const float* W = (const float*)d_in[2];
    const float* a1 = (const float*)d_in[3];
    const float* a2 = (const float*)d_in[4];
    const float* W1 = (const float*)d_in[5];
    const float* b1 = (const float*)d_in[6];
    const float* gamma = (const float*)d_in[7];
    const float* beta = (const float*)d_in[8];
    float* out = (float*)d_out;

    k_wh<<<dim3(NN / 32, HH), 128>>>(nodes, W);
    k_f<<<(HH * NN) / 8, 256>>>(a1, a2);
    k_rowmax<<<NN, 256>>>(adj);
    k_attn<<<dim3(HH, NN / 32), 256>>>(adj);   // h fast: 8 heads share adj rows in L2
    k_final<<<NN / 32, 256>>>(nodes, W1, b1, gamma, beta, out);
}

// round 3
// speedup vs baseline: 4.3483x; 4.3483x over previous
#include <cuda_runtime.h>
#include <cuda_bf16.h>
#include <cstdint>

#define NN 4096
#define DD 128
#define HH 8
#define ALPHA 0.2f
#define EPSLN 1e-5f

// ---------------- scratch ----------------
__device__ __nv_bfloat16 g_Whb[HH * NN * DD];   // [h][m][e] bf16 row-major (MMA B)
__device__ float g_attn[HH * NN * DD];          // attention out (pre-ELU), fp32
__device__ float g_f1[HH * NN];
__device__ float g_f2[HH * NN];
__device__ float g_f2t[NN * HH];
__device__ float g_rowmax[HH * NN];
__device__ float g_wa1[HH * DD];
__device__ float g_wa2[HH * DD];
__device__ unsigned g_adjbits[NN * (NN / 32)];  // 2MB bitmask

// ---------------- helpers ----------------
__device__ __forceinline__ uint32_t smem_u32(const void* p) {
    uint32_t a;
    asm("{ .reg .u64 t; cvta.to.shared.u64 t, %1; cvt.u32.u64 %0, t; }" : "=r"(a) : "l"(p));
    return a;
}
__device__ __forceinline__ void cp_async16(uint32_t sdst, const void* gsrc) {
    asm volatile("cp.async.cg.shared.global [%0], [%1], 16;" :: "r"(sdst), "l"(gsrc) : "memory");
}
__device__ __forceinline__ void cp_commit() {
    asm volatile("cp.async.commit_group;" ::: "memory");
}
__device__ __forceinline__ void cp_wait1() {
    asm volatile("cp.async.wait_group 1;" ::: "memory");
}
__device__ __forceinline__ void ldmatrix_x4_trans(uint32_t& b0, uint32_t& b1, uint32_t& b2,
                                                  uint32_t& b3, uint32_t addr) {
    asm volatile("ldmatrix.sync.aligned.m8n8.x4.trans.shared.b16 {%0,%1,%2,%3}, [%4];"
                 : "=r"(b0), "=r"(b1), "=r"(b2), "=r"(b3) : "r"(addr));
}
__device__ __forceinline__ void mma16816(float* c, uint32_t a0, uint32_t a1, uint32_t a2,
                                         uint32_t a3, uint32_t b0, uint32_t b1) {
    asm volatile(
        "mma.sync.aligned.m16n8k16.row.col.f32.bf16.bf16.f32 "
        "{%0,%1,%2,%3}, {%4,%5,%6,%7}, {%8,%9}, {%0,%1,%2,%3};"
        : "+f"(c[0]), "+f"(c[1]), "+f"(c[2]), "+f"(c[3])
        : "r"(a0), "r"(a1), "r"(a2), "r"(a3), "r"(b0), "r"(b1));
}
// swizzled 16B-chunk index within a 256B row
__device__ __forceinline__ uint32_t swz(uint32_t j, uint32_t row) {
    return (j & 8u) | ((j ^ row) & 7u);
}

// ============================================================
// K_wh: Wh[h] = nodes @ W[h]; emit bf16 row-major [h][m][e].
// ============================================================
__global__ void __launch_bounds__(128) k_wh(const float* __restrict__ nodes,
                                            const float* __restrict__ W) {
    int h = blockIdx.y;
    int n0 = blockIdx.x * 32;
    int e = threadIdx.x;
    __shared__ float xs[32][DD];
#pragma unroll
    for (int r = 0; r < 32; ++r) xs[r][e] = nodes[(n0 + r) * DD + e];
    __syncthreads();
    float acc[32];
#pragma unroll
    for (int r = 0; r < 32; ++r) acc[r] = 0.f;
    const float* Wp = W + h * DD * DD + e;
    for (int k = 0; k < DD; k += 4) {
        float w0 = Wp[(k + 0) * DD], w1 = Wp[(k + 1) * DD];
        float w2 = Wp[(k + 2) * DD], w3 = Wp[(k + 3) * DD];
#pragma unroll
        for (int r = 0; r < 32; ++r) {
            float4 x4 = *(const float4*)&xs[r][k];
            float a = acc[r];
            a = fmaf(x4.x, w0, a); a = fmaf(x4.y, w1, a);
            a = fmaf(x4.z, w2, a); a = fmaf(x4.w, w3, a);
            acc[r] = a;
        }
    }
    __syncthreads();
#pragma unroll
    for (int r = 0; r < 32; ++r) xs[r][e] = acc[r];
    __syncthreads();
#pragma unroll
    for (int i = 0; i < 4; ++i) {
        int u = threadIdx.x + i * 128;  // 0..511
        int row = u >> 4, j = u & 15;
        const float* xp = &xs[row][j * 8];
        uint32_t wd[4];
#pragma unroll
        for (int jj = 0; jj < 4; ++jj) {
            __nv_bfloat162 v = __floats2bfloat162_rn(xp[jj * 2], xp[jj * 2 + 1]);
            wd[jj] = *(uint32_t*)&v;
        }
        *(uint4*)&g_Whb[((long long)h * NN + n0 + row) * DD + j * 8] =
            make_uint4(wd[0], wd[1], wd[2], wd[3]);
    }
}

// ============================================================
// K_wa: wa1[h][d] = sum_e W[h][d][e]*a1[h][e]  (and wa2).
// ============================================================
__global__ void __launch_bounds__(256) k_wa(const float* __restrict__ W,
                                            const float* __restrict__ a1,
                                            const float* __restrict__ a2) {
    int wid = threadIdx.x >> 5, lane = threadIdx.x & 31;
    int idx = blockIdx.x * 8 + wid;  // 0..1023
    int h = idx >> 7, d = idx & 127;
    float4 wv = *(const float4*)&W[(h * DD + d) * DD + lane * 4];
    float4 av = *(const float4*)&a1[h * DD + lane * 4];
    float4 bv = *(const float4*)&a2[h * DD + lane * 4];
    float s1 = wv.x * av.x + wv.y * av.y + wv.z * av.z + wv.w * av.w;
    float s2 = wv.x * bv.x + wv.y * bv.y + wv.z * bv.z + wv.w * bv.w;
#pragma unroll
    for (int o = 16; o; o >>= 1) {
        s1 += __shfl_xor_sync(0xffffffffu, s1, o);
        s2 += __shfl_xor_sync(0xffffffffu, s2, o);
    }
    if (lane == 0) { g_wa1[idx] = s1; g_wa2[idx] = s2; }
}

// ============================================================
// K_f: f1[h][n] = nodes[n]·wa1[h]; f2 likewise; f2t transposed.
// ============================================================
__global__ void __launch_bounds__(256) k_f(const float* __restrict__ nodes) {
    __shared__ float w1s[HH * DD], w2s[HH * DD];
    int t = threadIdx.x;
    for (int i = t; i < HH * DD; i += 256) { w1s[i] = g_wa1[i]; w2s[i] = g_wa2[i]; }
    __syncthreads();
    int wid = t >> 5, lane = t & 31;
    int n = blockIdx.x * 8 + wid;
    float4 x = *(const float4*)&nodes[n * DD + lane * 4];
#pragma unroll
    for (int h = 0; h < HH; ++h) {
        float4 w1 = *(const float4*)&w1s[h * DD + lane * 4];
        float4 w2 = *(const float4*)&w2s[h * DD + lane * 4];
        float s1 = x.x * w1.x + x.y * w1.y + x.z * w1.z + x.w * w1.w;
        float s2 = x.x * w2.x + x.y * w2.y + x.z * w2.z + x.w * w2.w;
#pragma unroll
        for (int o = 16; o; o >>= 1) {
            s1 += __shfl_xor_sync(0xffffffffu, s1, o);
            s2 += __shfl_xor_sync(0xffffffffu, s2, o);
        }
        if (lane == 0) {
            g_f1[h * NN + n] = s1;
            g_f2[h * NN + n] = s2;
            g_f2t[n * HH + h] = s2;
        }
    }
}

// ============================================================
// K_bits: pack adj>0 into bitmask.
// ============================================================
__global__ void __launch_bounds__(256) k_bits(const int* __restrict__ adj) {
    int n = blockIdx.x;
    int wid = threadIdx.x >> 5, lane = threadIdx.x & 31;
    for (int j = wid; j < NN / 32; j += 8) {
        int v = adj[(long long)n * NN + j * 32 + lane];
        unsigned bal = __ballot_sync(0xffffffffu, v > 0);
        if (lane == 0) g_adjbits[n * (NN / 32) + j] = bal;
    }
}

// ============================================================
// K_rowmax: masked max of f2 over neighbors (8 heads, bitmask driven).
// ============================================================
__global__ void __launch_bounds__(256) k_rowmax() {
    int n = blockIdx.x;
    int t = threadIdx.x;
    float mx[8];
#pragma unroll
    for (int i = 0; i < 8; ++i) mx[i] = -1e30f;
    unsigned bits = (g_adjbits[n * (NN / 32) + (t >> 1)] >> ((t & 1) * 16)) & 0xFFFFu;
    int mbase = (t >> 1) * 32 + (t & 1) * 16;
    while (bits) {
        int k = __ffs(bits) - 1;
        bits &= bits - 1;
        float4 fa = *(const float4*)&g_f2t[(mbase + k) * HH];
        float4 fb = *(const float4*)&g_f2t[(mbase + k) * HH + 4];
        mx[0] = fmaxf(mx[0], fa.x); mx[1] = fmaxf(mx[1], fa.y);
        mx[2] = fmaxf(mx[2], fa.z); mx[3] = fmaxf(mx[3], fa.w);
        mx[4] = fmaxf(mx[4], fb.x); mx[5] = fmaxf(mx[5], fb.y);
        mx[6] = fmaxf(mx[6], fb.z); mx[7] = fmaxf(mx[7], fb.w);
    }
#pragma unroll
    for (int i = 0; i < 8; ++i)
#pragma unroll
        for (int o = 16; o; o >>= 1) mx[i] = fmaxf(mx[i], __shfl_xor_sync(0xffffffffu, mx[i], o));
    __shared__ float smx[8][8];
    if ((t & 31) == 0) {
        int w = t >> 5;
#pragma unroll
        for (int i = 0; i < 8; ++i) smx[w][i] = mx[i];
    }
    __syncthreads();
    if (t < 8) {
        float m = smx[0][t];
#pragma unroll
        for (int w = 1; w < 8; ++w) m = fmaxf(m, smx[w][t]);
        g_rowmax[t * NN + n] = m;
    }
}

// ============================================================
// K_attn: D[128n,128e] = softmax-agg via mma.sync bf16 (base-ISA tensor cores).
// Warp w: rows [w*16, w*16+16), all 128 cols. K chunks of 64 (double-buffered B).
// P generated directly into A-fragment registers (exp once per (n,m)).
// ============================================================
#define KC 64
#define BBYTES (KC * 256)         // 16KB per B buffer
#define SM_F2 (2 * BBYTES)        // f2 row at 32KB
#define ATTN_SMEM (SM_F2 + NN * 4)

__device__ __forceinline__ float lrelu(float s) { return s > 0.f ? s : ALPHA * s; }

__global__ void __launch_bounds__(256, 2) k_attn() {
    extern __shared__ char smem[];
    uint32_t sbase = smem_u32(smem);
    float* f2s = (float*)(smem + SM_F2);
    int h = blockIdx.x;
    int n0 = blockIdx.y * 128;
    int t = threadIdx.x;
    int lane = t & 31, w = t >> 5;

    // ---- preload B chunk 0 (overlaps f2 staging) ----
    const __nv_bfloat16* whb = &g_Whb[(long long)h * NN * DD];
    {
#pragma unroll
        for (int i = 0; i < 4; ++i) {
            int u = t + i * 256;  // 0..1023
            uint32_t row = u >> 4, j = u & 15;
            cp_async16(sbase + row * 256 + (swz(j, row) << 4),
                       whb + (long long)row * DD + j * 8);
        }
        cp_commit();
    }
    // ---- stage f2[h][*] into smem ----
    {
        const float4* src = (const float4*)(g_f2 + h * NN);
        float4* dst = (float4*)f2s;
        for (int i = t; i < NN / 4; i += 256) dst[i] = src[i];
    }

    // per-thread row constants
    int qr = lane >> 2;          // 0..7
    int ko = (lane & 3) * 2;     // 0,2,4,6
    int gn0 = n0 + w * 16 + qr;
    int gn1 = gn0 + 8;
    float f1_0 = g_f1[h * NN + gn0];
    float f1_1 = g_f1[h * NN + gn1];
    float mx0 = lrelu(f1_0 + g_rowmax[h * NN + gn0]);
    float mx1 = lrelu(f1_1 + g_rowmax[h * NN + gn1]);
    const uint2* bp0 = (const uint2*)&g_adjbits[(long long)gn0 * (NN / 32)];
    const uint2* bp1 = (const uint2*)&g_adjbits[(long long)gn1 * (NN / 32)];
    float rs0 = 0.f, rs1 = 0.f;
    float c[16][4];
#pragma unroll
    for (int j = 0; j < 16; ++j) { c[j][0] = c[j][1] = c[j][2] = c[j][3] = 0.f; }

    int lr16 = lane & 15;   // ldmatrix row within k16
    int hi = lane >> 4;     // col half for x4

    for (int ch = 0; ch < NN / KC; ++ch) {
        uint32_t bcur = sbase + (ch & 1) * BBYTES;
        // issue next chunk's B loads into other buffer
        if (ch + 1 < NN / KC) {
            uint32_t bnext = sbase + ((ch + 1) & 1) * BBYTES;
            const __nv_bfloat16* src = whb + (long long)(ch + 1) * KC * DD;
#pragma unroll
            for (int i = 0; i < 4; ++i) {
                int u = t + i * 256;
                uint32_t row = u >> 4, j = u & 15;
                cp_async16(bnext + row * 256 + (swz(j, row) << 4),
                           src + (long long)row * DD + j * 8);
            }
        }
        cp_commit();
        cp_wait1();          // chunk ch resident (this thread)
        __syncthreads();     // visible to all

        uint2 bw0 = bp0[ch], bw1 = bp1[ch];
        unsigned long long b0 = (unsigned long long)bw0.x | ((unsigned long long)bw0.y << 32);
        unsigned long long b1 = (unsigned long long)bw1.x | ((unsigned long long)bw1.y << 32);

#pragma unroll
        for (int s = 0; s < 4; ++s) {
            int mb = ch * KC + s * 16;
            float2 fA = *(const float2*)&f2s[mb + ko];
            float2 fB = *(const float2*)&f2s[mb + ko + 8];
            int sb = s * 16 + ko;
            float p00 = ((b0 >> sb) & 1ull) ? __expf(lrelu(f1_0 + fA.x) - mx0) : 0.f;
            float p01 = ((b0 >> (sb + 1)) & 1ull) ? __expf(lrelu(f1_0 + fA.y) - mx0) : 0.f;
            float p02 = ((b0 >> (sb + 8)) & 1ull) ? __expf(lrelu(f1_0 + fB.x) - mx0) : 0.f;
            float p03 = ((b0 >> (sb + 9)) & 1ull) ? __expf(lrelu(f1_0 + fB.y) - mx0) : 0.f;
            float p10 = ((b1 >> sb) & 1ull) ? __expf(lrelu(f1_1 + fA.x) - mx1) : 0.f;
            float p11 = ((b1 >> (sb + 1)) & 1ull) ? __expf(lrelu(f1_1 + fA.y) - mx1) : 0.f;
            float p12 = ((b1 >> (sb + 8)) & 1ull) ? __expf(lrelu(f1_1 + fB.x) - mx1) : 0.f;
            float p13 = ((b1 >> (sb + 9)) & 1ull) ? __expf(lrelu(f1_1 + fB.y) - mx1) : 0.f;
            __nv_bfloat162 A0 = __floats2bfloat162_rn(p00, p01);
            __nv_bfloat162 A1 = __floats2bfloat162_rn(p10, p11);
            __nv_bfloat162 A2 = __floats2bfloat162_rn(p02, p03);
            __nv_bfloat162 A3 = __floats2bfloat162_rn(p12, p13);
            // row-sum from the bf16-rounded values (matches MMA numerator)
            rs0 += __low2float(A0) + __high2float(A0) + __low2float(A2) + __high2float(A2);
            rs1 += __low2float(A1) + __high2float(A1) + __low2float(A3) + __high2float(A3);
            uint32_t a0 = *(uint32_t*)&A0, a1 = *(uint32_t*)&A1;
            uint32_t a2 = *(uint32_t*)&A2, a3 = *(uint32_t*)&A3;

            uint32_t lrow = (uint32_t)(s * 16 + lr16);
            uint32_t rowb = bcur + lrow * 256;
#pragma unroll
            for (int jj = 0; jj < 8; ++jj) {
                uint32_t j2 = (uint32_t)(jj * 2 + hi);
                uint32_t addr = rowb + (swz(j2, lrow) << 4);
                uint32_t v0, v1, v2, v3;
                ldmatrix_x4_trans(v0, v1, v2, v3, addr);
                mma16816(c[jj * 2], a0, a1, a2, a3, v0, v1);
                mma16816(c[jj * 2 + 1], a0, a1, a2, a3, v2, v3);
            }
        }
        __syncthreads();
    }

    // quad-reduce row sums (lanes sharing t/4)
    rs0 += __shfl_xor_sync(0xffffffffu, rs0, 1);
    rs0 += __shfl_xor_sync(0xffffffffu, rs0, 2);
    rs1 += __shfl_xor_sync(0xffffffffu, rs1, 1);
    rs1 += __shfl_xor_sync(0xffffffffu, rs1, 2);
    float inv0 = 1.f / rs0, inv1 = 1.f / rs1;

    float* o0 = &g_attn[((long long)h * NN + gn0) * DD];
    float* o1 = &g_attn[((long long)h * NN + gn1) * DD];
#pragma unroll
    for (int j = 0; j < 16; ++j) {
        float2 v;
        v.x = c[j][0] * inv0; v.y = c[j][1] * inv0;
        *(float2*)&o0[j * 8 + ko] = v;
        v.x = c[j][2] * inv1; v.y = c[j][3] * inv1;
        *(float2*)&o1[j * 8 + ko] = v;
    }
}

// ============================================================
// K_final: x = elu(elu(cat)@W1 + b1); out = LN(nodes + x)*gamma + beta.
// ============================================================
__global__ void __launch_bounds__(256) k_final(const float* __restrict__ nodes,
                                               const float* __restrict__ W1,
                                               const float* __restrict__ b1,
                                               const float* __restrict__ gamma,
                                               const float* __restrict__ beta,
                                               float* __restrict__ out) {
    int n0 = blockIdx.x * 32;
    int t = threadIdx.x;
    int lane = t & 31, w = t >> 5;
    int e2 = lane * 4;
    __shared__ float As[32][64];
    __shared__ float Bs[64][DD];
    float4 acc[4];
#pragma unroll
    for (int rr = 0; rr < 4; ++rr) acc[rr] = make_float4(0.f, 0.f, 0.f, 0.f);

    for (int k0 = 0; k0 < HH * DD; k0 += 64) {
        __syncthreads();
        for (int idx = t; idx < 32 * 64; idx += 256) {
            int row = idx >> 6, kk = idx & 63;
            int k = k0 + kk;
            int hh = k >> 7, e = k & 127;
            float v = g_attn[(hh * NN + n0 + row) * DD + e];
            As[row][kk] = v > 0.f ? v : expm1f(v);
        }
        for (int idx = t; idx < 64 * DD; idx += 256) {
            int kk = idx >> 7, e = idx & 127;
            Bs[kk][e] = W1[(k0 + kk) * DD + e];
        }
        __syncthreads();
#pragma unroll 4
        for (int kk = 0; kk < 64; ++kk) {
            float4 b4 = *(const float4*)&Bs[kk][e2];
#pragma unroll
            for (int rr = 0; rr < 4; ++rr) {
                float a = As[w * 4 + rr][kk];
                acc[rr].x = fmaf(a, b4.x, acc[rr].x);
                acc[rr].y = fmaf(a, b4.y, acc[rr].y);
                acc[rr].z = fmaf(a, b4.z, acc[rr].z);
                acc[rr].w = fmaf(a, b4.w, acc[rr].w);
            }
        }
    }

    float4 bb = *(const float4*)&b1[e2];
    float4 gg = *(const float4*)&gamma[e2];
    float4 be = *(const float4*)&beta[e2];
#pragma unroll
    for (int rr = 0; rr < 4; ++rr) {
        int n = n0 + w * 4 + rr;
        float4 x = acc[rr];
        x.x += bb.x; x.y += bb.y; x.z += bb.z; x.w += bb.w;
        x.x = x.x > 0.f ? x.x : expm1f(x.x);
        x.y = x.y > 0.f ? x.y : expm1f(x.y);
        x.z = x.z > 0.f ? x.z : expm1f(x.z);
        x.w = x.w > 0.f ? x.w : expm1f(x.w);
        float4 nd = *(const float4*)&nodes[n * DD + e2];
        float4 y = make_float4(nd.x + x.x, nd.y + x.y, nd.z + x.z, nd.w + x.w);
        float s = y.x + y.y + y.z + y.w;
        float q = y.x * y.x + y.y * y.y + y.z * y.z + y.w * y.w;
#pragma unroll
        for (int o = 16; o; o >>= 1) {
            s += __shfl_xor_sync(0xffffffffu, s, o);
            q += __shfl_xor_sync(0xffffffffu, q, o);
        }
        float mu = s * (1.f / 128.f);
        float var = q * (1.f / 128.f) - mu * mu;
        float rs = rsqrtf(var + EPSLN);
        float4 o4;
        o4.x = (y.x - mu) * rs * gg.x + be.x;
        o4.y = (y.y - mu) * rs * gg.y + be.y;
        o4.z = (y.z - mu) * rs * gg.z + be.z;
        o4.w = (y.w - mu) * rs * gg.w + be.w;
        *(float4*)&out[n * DD + e2] = o4;
    }
}

extern "C" void kernel_launch(void* const* d_in, const int* in_sizes, int n_in,
                              void* d_out, int out_size) {
    const float* nodes = (const float*)d_in[0];
    const int* adj = (const int*)d_in[1];
    const float* W = (const float*)d_in[2];
    const float* a1 = (const float*)d_in[3];
    const float* a2 = (const float*)d_in[4];
    const float* W1 = (const float*)d_in[5];
    const float* b1 = (const float*)d_in[6];
    const float* gamma = (const float*)d_in[7];
    const float* beta = (const float*)d_in[8];
    float* out = (float*)d_out;

    cudaFuncSetAttribute(k_attn, cudaFuncAttributeMaxDynamicSharedMemorySize, ATTN_SMEM);

    k_bits<<<NN, 256>>>(adj);
    k_wa<<<128, 256>>>(W, a1, a2);
    k_f<<<NN / 8, 256>>>(nodes);
    k_rowmax<<<NN, 256>>>();
    k_wh<<<dim3(NN / 32, HH), 128>>>(nodes, W);
    k_attn<<<dim3(HH, NN / 128), 256, ATTN_SMEM>>>();
    k_final<<<NN / 32, 256>>>(nodes, W1, b1, gamma, beta, out);
}